// round 13
// baseline (speedup 1.0000x reference)
#include <cuda_runtime.h>
#include <cuda_fp16.h>

#define Hh   512
#define Bb   32
#define Tt   2048
#define W3H  1536

// ---------------- device scratch ----------------
__device__ float g_u[Bb * Hh];      // W1@hidden + b_attn
__device__ float g_w3c[Hh];         // W3 @ W_cov
__device__ float g_scores[Bb * Tt]; // pre-softmax scores
__device__ __half g_w2h[Hh * Hh];   // W2 in fp16, [h][k]

// ---------------- PTX helpers (baseline ISA only) ----------------
static __device__ __forceinline__ unsigned smem_u32(const void* p) {
    unsigned a;
    asm("{ .reg .u64 t; cvta.to.shared.u64 t, %1; cvt.u32.u64 %0, t; }" : "=r"(a) : "l"(p));
    return a;
}

#define LDSM_X4(r, a) \
    asm volatile("ldmatrix.sync.aligned.m8n8.x4.shared.b16 {%0,%1,%2,%3}, [%4];" \
        : "=r"((r)[0]), "=r"((r)[1]), "=r"((r)[2]), "=r"((r)[3]) : "r"(a))

// fp16-accumulator MMA: d,c are 2x f16x2 regs
#define MMA_F16A(d, a, b0, b1) \
    asm volatile("mma.sync.aligned.m16n8k16.row.col.f16.f16.f16.f16 " \
        "{%0,%1}, {%2,%3,%4,%5}, {%6,%7}, {%0,%1};" \
        : "+r"((d)[0]), "+r"((d)[1]) \
        : "r"((a)[0]), "r"((a)[1]), "r"((a)[2]), "r"((a)[3]), "r"(b0), "r"(b1))

#define CP_ASYNC16(dst, src) \
    asm volatile("cp.async.cg.shared.global [%0], [%1], 16;" :: "r"(dst), "l"(src) : "memory")
#define CP_COMMIT() asm volatile("cp.async.commit_group;" ::: "memory")
#define CP_WAIT1()  asm volatile("cp.async.wait_group 1;" ::: "memory")

// swizzle: 128B rows, XOR bits[4:6] with row bits (row&7)
static __device__ __forceinline__ unsigned swz(unsigned o) { return o ^ ((o >> 3) & 0x70u); }

// ---------------- kernel 1: fused prep ----------------
// blocks 0..263: precompute u[b,h] / w3c[h]; blocks 264..391: W2 fp32 -> fp16
__global__ __launch_bounds__(512) void prep_kernel(
    const float* __restrict__ hidden, const float* __restrict__ W_attn,
    const float* __restrict__ b_attn, const float* __restrict__ W_cov)
{
    const int tx = threadIdx.x;
    if (blockIdx.x >= 264) {                     // ---- W2 convert (coalesced) ----
        int i = ((blockIdx.x - 264) * 512 + tx) * 4;
        int h = i >> 9, k = i & 511;
        float4 w = *(const float4*)(W_attn + (size_t)h * W3H + Hh + k);
        __half2 p0 = __floats2half2_rn(w.x, w.y);
        __half2 p1 = __floats2half2_rn(w.z, w.w);
        uint2 uu;
        uu.x = *reinterpret_cast<unsigned*>(&p0);
        uu.y = *reinterpret_cast<unsigned*>(&p1);
        *(uint2*)(g_w2h + i) = uu;
        return;
    }
    // ---- precompute: 8 threads per h-row, contiguous 128B per row-group ----
    __shared__ float sh[Hh];
    __shared__ float red[64][9];
    const int bx = blockIdx.x >> 3;              // 0..32
    const int hy = blockIdx.x & 7;               // 0..7
    sh[tx] = (bx < Bb) ? hidden[bx * Hh + tx] : W_cov[tx];
    __syncthreads();
    const int hl = tx >> 3, ks = tx & 7;
    const int h = hy * 64 + hl;
    const float* wr = W_attn + (size_t)h * W3H + (bx < Bb ? 0 : 2 * Hh);
    float a0 = 0.f, a1 = 0.f, a2 = 0.f, a3 = 0.f;
    #pragma unroll
    for (int j = 0; j < 16; j++) {
        const int k0 = j * 32 + ks * 4;          // warp: 4 rows x 128B contiguous
        float4 w = *(const float4*)(wr + k0);
        float4 s = *(const float4*)(sh + k0);
        a0 += w.x * s.x; a1 += w.y * s.y; a2 += w.z * s.z; a3 += w.w * s.w;
    }
    red[hl][ks] = (a0 + a1) + (a2 + a3);
    __syncthreads();
    if (tx < 64) {
        float s = 0.f;
        #pragma unroll
        for (int q = 0; q < 8; q++) s += red[tx][q];
        int hh = hy * 64 + tx;
        if (bx < Bb) g_u[bx * Hh + hh] = s + b_attn[hh];
        else         g_w3c[hh] = s;
    }
}

// ---------------- kernel 2: warp-MMA GEMM + fused epilogue -> scores ----------------
// 512 threads = 16 warps (4m x 4n), warp tile 32t x 32h.
// f16 accumulate per 64-k chunk, promoted to fp32 every chunk.
#define OFF_SU    0
#define OFF_SW3   2048
#define OFF_SV    4096
#define OFF_SRED  6144                 // 512 floats
#define OFF_A     8192                 // 8 k-sections x [128 rows x 128 B] = 131072
#define OFF_B     (8192 + 131072)      // 3 bufs x [128 rows x 128 B] = 49152
#define GEMM_SMEM (OFF_B + 49152)      // 188416

__global__ __launch_bounds__(512, 1)
void gemm_scores_kernel(const float* __restrict__ enc,
                        const float* __restrict__ coverage,
                        const float* __restrict__ v)
{
    extern __shared__ char smem[];
    const unsigned sb = smem_u32(smem);
    const int tx = threadIdx.x;
    const int wid = tx >> 5, l = tx & 31;
    const int mw = wid & 3, nw = wid >> 2;      // 4 m-warps x 4 n-warps
    const int b = blockIdx.y;
    const int t0 = blockIdx.x * 128;

    float* su  = (float*)(smem + OFF_SU);
    float* sw3 = (float*)(smem + OFF_SW3);
    float* sv  = (float*)(smem + OFF_SV);

    // ---- B chunk loader: chunk i -> (ht=i>>3, kc=i&7), buf i%3 (128h x 64k) ----
    auto load_b = [&](int i) {
        const int ht = i >> 3, kc = i & 7;
        const unsigned bufo = sb + OFF_B + (unsigned)(i % 3) * 16384;
        #pragma unroll
        for (int j = 0; j < 2; j++) {
            const int idx = tx + j * 512;
            const int row = idx >> 3;
            const int seg = idx & 7;
            const __half* src = g_w2h + (size_t)(ht * 128 + row) * Hh + kc * 64 + seg * 8;
            CP_ASYNC16(bufo + swz((unsigned)(row * 128 + seg * 16)), src);
        }
    };

    load_b(0); CP_COMMIT();
    load_b(1); CP_COMMIT();

    // ---- epilogue vectors ----
    for (int i = tx; i < Hh; i += 512) {
        su[i] = g_u[b * Hh + i]; sw3[i] = g_w3c[i]; sv[i] = v[i];
    }

    // ---- A tile: enc rows t0..t0+127 of batch b, fp32 -> fp16 swizzled smem ----
    {
        const int rs = tx >> 4, kg = tx & 15;
        #pragma unroll
        for (int rr = 0; rr < 4; rr++) {
            const int r = rr * 32 + rs;
            const float* rowp = enc + ((size_t)(t0 + r) * Bb + b) * Hh;
            #pragma unroll
            for (int kk = 0; kk < 8; kk++) {
                const int k0 = kk * 64 + kg * 4;
                float4 e = *(const float4*)(rowp + k0);
                __half2 p0 = __floats2half2_rn(e.x, e.y);
                __half2 p1 = __floats2half2_rn(e.z, e.w);
                uint2 uu;
                uu.x = *reinterpret_cast<unsigned*>(&p0);
                uu.y = *reinterpret_cast<unsigned*>(&p1);
                *(uint2*)(smem + OFF_A + kk * 16384 +
                          swz((unsigned)(r * 128 + (k0 & 63) * 2))) = uu;
            }
        }
    }

    // ---- per-lane ldmatrix address precompute ----
    unsigned aBase[2], aXor[2];
    {
        const int rA = mw * 32 + ((l >> 3) & 1) * 8 + (l & 7);
        #pragma unroll
        for (int mi = 0; mi < 2; mi++) {
            const int row = rA + mi * 16;
            aBase[mi] = sb + OFF_A + (unsigned)(row * 128);
            aXor[mi]  = (unsigned)((row & 7) << 4);
        }
    }
    const int cbA = ((l >> 4) & 1) * 8;
    unsigned bBase[2], bXor[2];
    {
        const int rB = nw * 32 + ((l >> 4) & 1) * 8 + (l & 7);
        #pragma unroll
        for (int nj = 0; nj < 2; nj++) {
            const int row = rB + nj * 16;
            bBase[nj] = sb + OFF_B + (unsigned)(row * 128);
            bXor[nj]  = (unsigned)((row & 7) << 4);
        }
    }
    const int cbB = ((l >> 3) & 1) * 8;

    float cov[4];
    #pragma unroll
    for (int mi = 0; mi < 2; mi++)
        #pragma unroll
        for (int half = 0; half < 2; half++)
            cov[mi * 2 + half] =
                coverage[b * Tt + t0 + mw * 32 + mi * 16 + (l >> 2) + half * 8];

    float acc[2][4][4];                 // fp32 shadow accumulators
    float sc[4] = {0.f, 0.f, 0.f, 0.f};
    const int c0 = (l & 3) * 2;

    // ---- main pipeline: 32 chunks (4 h-tiles x 8 k-chunks of 64), 3 stages ----
    for (int i = 0; i < 32; i++) {
        CP_WAIT1();
        __syncthreads();
        if (i + 2 < 32) load_b(i + 2);
        CP_COMMIT();

        const int kc = i & 7, ht = i >> 3;
        if (kc == 0) {
            #pragma unroll
            for (int mi = 0; mi < 2; mi++)
                #pragma unroll
                for (int ni = 0; ni < 4; ni++)
                    #pragma unroll
                    for (int q = 0; q < 4; q++) acc[mi][ni][q] = 0.f;
        }

        // f16 accumulators for this 64-k chunk
        unsigned hacc[2][4][2];
        #pragma unroll
        for (int mi = 0; mi < 2; mi++)
            #pragma unroll
            for (int ni = 0; ni < 4; ni++) { hacc[mi][ni][0] = 0u; hacc[mi][ni][1] = 0u; }

        const unsigned aS = (unsigned)kc * 16384;
        const unsigned bS = (unsigned)(i % 3) * 16384;
        #pragma unroll
        for (int s = 0; s < 4; s++) {
            const unsigned colA = (unsigned)((s * 16 + cbA) * 2);
            const unsigned colB = (unsigned)((s * 16 + cbB) * 2);
            unsigned av[2][4], bv[2][4];
            LDSM_X4(av[0], aBase[0] + aS + (colA ^ aXor[0]));
            LDSM_X4(av[1], aBase[1] + aS + (colA ^ aXor[1]));
            LDSM_X4(bv[0], bBase[0] + bS + (colB ^ bXor[0]));
            LDSM_X4(bv[1], bBase[1] + bS + (colB ^ bXor[1]));
            #pragma unroll
            for (int mi = 0; mi < 2; mi++) {
                MMA_F16A(hacc[mi][0], av[mi], bv[0][0], bv[0][1]);
                MMA_F16A(hacc[mi][1], av[mi], bv[0][2], bv[0][3]);
                MMA_F16A(hacc[mi][2], av[mi], bv[1][0], bv[1][1]);
                MMA_F16A(hacc[mi][3], av[mi], bv[1][2], bv[1][3]);
            }
        }

        // promote chunk sums to fp32
        #pragma unroll
        for (int mi = 0; mi < 2; mi++)
            #pragma unroll
            for (int ni = 0; ni < 4; ni++) {
                float2 f0 = __half22float2(*reinterpret_cast<__half2*>(&hacc[mi][ni][0]));
                float2 f1 = __half22float2(*reinterpret_cast<__half2*>(&hacc[mi][ni][1]));
                acc[mi][ni][0] += f0.x; acc[mi][ni][1] += f0.y;
                acc[mi][ni][2] += f1.x; acc[mi][ni][3] += f1.y;
            }

        if (kc == 7) {
            // epilogue for h-tile ht: energy + u + cov*w3c -> relu -> dot v
            #pragma unroll
            for (int ni = 0; ni < 4; ni++) {
                const int h = ht * 128 + nw * 32 + ni * 8 + c0;
                const float2 u2 = *(const float2*)&su[h];
                const float2 w2 = *(const float2*)&sw3[h];
                const float2 v2 = *(const float2*)&sv[h];
                #pragma unroll
                for (int mi = 0; mi < 2; mi++) {
                    float e0 = acc[mi][ni][0] + u2.x + cov[mi * 2] * w2.x;
                    float e1 = acc[mi][ni][1] + u2.y + cov[mi * 2] * w2.y;
                    sc[mi * 2] += v2.x * fmaxf(e0, 0.f) + v2.y * fmaxf(e1, 0.f);
                    float e2 = acc[mi][ni][2] + u2.x + cov[mi * 2 + 1] * w2.x;
                    float e3 = acc[mi][ni][3] + u2.y + cov[mi * 2 + 1] * w2.y;
                    sc[mi * 2 + 1] += v2.x * fmaxf(e2, 0.f) + v2.y * fmaxf(e3, 0.f);
                }
            }
        }
    }

    // ---- reduce: 4 lanes per row, then 4 n-warp groups ----
    #pragma unroll
    for (int q = 1; q < 4; q <<= 1)
        #pragma unroll
        for (int j = 0; j < 4; j++)
            sc[j] += __shfl_xor_sync(0xFFFFFFFFu, sc[j], q);

    float* sred = (float*)(smem + OFF_SRED);
    __syncthreads();
    if ((l & 3) == 0) {
        #pragma unroll
        for (int mi = 0; mi < 2; mi++)
            #pragma unroll
            for (int half = 0; half < 2; half++)
                sred[nw * 128 + mw * 32 + mi * 16 + (l >> 2) + half * 8] = sc[mi * 2 + half];
    }
    __syncthreads();
    if (tx < 128)
        g_scores[b * Tt + t0 + tx] =
            (sred[tx] + sred[128 + tx]) + (sred[256 + tx] + sred[384 + tx]);
}

// ---------------- kernel 3: softmax over T + coverage update ----------------
__global__ __launch_bounds__(512) void softmax_kernel(
    const float* __restrict__ coverage, float* __restrict__ out, int write_cov)
{
    __shared__ float red[16];
    const int b = blockIdx.x, tx = threadIdx.x;
    const int wi = tx >> 5, li = tx & 31;
    const float* s = g_scores + b * Tt;

    float4 x = ((const float4*)s)[tx];

    float m = fmaxf(fmaxf(x.x, x.y), fmaxf(x.z, x.w));
    #pragma unroll
    for (int q = 16; q > 0; q >>= 1) m = fmaxf(m, __shfl_xor_sync(0xFFFFFFFFu, m, q));
    if (li == 0) red[wi] = m;
    __syncthreads();
    if (tx < 32) {
        float mm = (tx < 16) ? red[tx] : -3.0e38f;
        #pragma unroll
        for (int q = 8; q > 0; q >>= 1) mm = fmaxf(mm, __shfl_xor_sync(0xFFFFFFFFu, mm, q));
        if (tx == 0) red[0] = mm;
    }
    __syncthreads();
    m = red[0];

    float4 e;
    e.x = __expf(x.x - m); e.y = __expf(x.y - m);
    e.z = __expf(x.z - m); e.w = __expf(x.w - m);
    float sum = (e.x + e.y) + (e.z + e.w);
    #pragma unroll
    for (int q = 16; q > 0; q >>= 1) sum += __shfl_xor_sync(0xFFFFFFFFu, sum, q);
    __syncthreads();
    if (li == 0) red[wi] = sum;
    __syncthreads();
    if (tx < 32) {
        float ss = (tx < 16) ? red[tx] : 0.f;
        #pragma unroll
        for (int q = 8; q > 0; q >>= 1) ss += __shfl_xor_sync(0xFFFFFFFFu, ss, q);
        if (tx == 0) red[0] = ss;
    }
    __syncthreads();
    const float inv = 1.f / red[0];

    float4 w;
    w.x = e.x * inv; w.y = e.y * inv; w.z = e.z * inv; w.w = e.w * inv;
    ((float4*)(out + b * Tt))[tx] = w;
    if (write_cov) {
        float4 c = ((const float4*)(coverage + b * Tt))[tx];
        c.x += w.x; c.y += w.y; c.z += w.z; c.w += w.w;
        ((float4*)(out + Bb * Tt + b * Tt))[tx] = c;
    }
}

// ---------------- launch ----------------
extern "C" void kernel_launch(void* const* d_in, const int* in_sizes, int n_in,
                              void* d_out, int out_size) {
    const float* hidden   = (const float*)d_in[0];
    const float* enc      = (const float*)d_in[1];
    const float* coverage = (const float*)d_in[2];
    const float* W_attn   = (const float*)d_in[3];
    const float* b_attn   = (const float*)d_in[4];
    const float* v        = (const float*)d_in[5];
    const float* W_cov    = (const float*)d_in[6];
    float* out = (float*)d_out;

    cudaFuncSetAttribute(gemm_scores_kernel,
                         cudaFuncAttributeMaxDynamicSharedMemorySize, GEMM_SMEM);

    prep_kernel<<<392, 512>>>(hidden, W_attn, b_attn, W_cov);
    gemm_scores_kernel<<<dim3(Tt / 128, Bb), 512, GEMM_SMEM>>>(enc, coverage, v);

    const int write_cov = (out_size >= 2 * Bb * Tt) ? 1 : 0;
    softmax_kernel<<<Bb, 512>>>(coverage, out, write_cov);
}

// round 15
// speedup vs baseline: 1.3396x; 1.3396x over previous
#include <cuda_runtime.h>
#include <cuda_fp16.h>

#define Hh   512
#define Bb   32
#define Tt   2048
#define W3H  1536

// ---------------- device scratch ----------------
__device__ float g_u[Bb * Hh];      // W1@hidden + b_attn
__device__ float g_w3c[Hh];         // W3 @ W_cov
__device__ float g_scores[Bb * Tt]; // pre-softmax scores
__device__ __half g_w2h[Hh * Hh];   // W2 in fp16, [h][k]

// ---------------- PTX helpers (baseline ISA only) ----------------
static __device__ __forceinline__ unsigned smem_u32(const void* p) {
    unsigned a;
    asm("{ .reg .u64 t; cvta.to.shared.u64 t, %1; cvt.u32.u64 %0, t; }" : "=r"(a) : "l"(p));
    return a;
}

#define LDSM_X4(r, a) \
    asm volatile("ldmatrix.sync.aligned.m8n8.x4.shared.b16 {%0,%1,%2,%3}, [%4];" \
        : "=r"((r)[0]), "=r"((r)[1]), "=r"((r)[2]), "=r"((r)[3]) : "r"(a))

#define MMA_F16(c, a, b0, b1) \
    asm volatile("mma.sync.aligned.m16n8k16.row.col.f32.f16.f16.f32 " \
        "{%0,%1,%2,%3}, {%4,%5,%6,%7}, {%8,%9}, {%0,%1,%2,%3};" \
        : "+f"((c)[0]), "+f"((c)[1]), "+f"((c)[2]), "+f"((c)[3]) \
        : "r"((a)[0]), "r"((a)[1]), "r"((a)[2]), "r"((a)[3]), "r"(b0), "r"(b1))

#define CP_ASYNC16(dst, src) \
    asm volatile("cp.async.cg.shared.global [%0], [%1], 16;" :: "r"(dst), "l"(src) : "memory")
#define CP_COMMIT() asm volatile("cp.async.commit_group;" ::: "memory")
#define CP_WAIT0()  asm volatile("cp.async.wait_group 0;" ::: "memory")

// swizzle: 128B rows, XOR bits[4:6] with row bits (row&7)
static __device__ __forceinline__ unsigned swz(unsigned o) { return o ^ ((o >> 3) & 0x70u); }

// ---------------- kernel 1: fused prep ----------------
// blocks 0..263: precompute u[b,h] / w3c[h]; blocks 264..391: W2 fp32 -> fp16
__global__ __launch_bounds__(512) void prep_kernel(
    const float* __restrict__ hidden, const float* __restrict__ W_attn,
    const float* __restrict__ b_attn, const float* __restrict__ W_cov)
{
    const int tx = threadIdx.x;
    if (blockIdx.x >= 264) {                     // ---- W2 convert (coalesced) ----
        int i = ((blockIdx.x - 264) * 512 + tx) * 4;
        int h = i >> 9, k = i & 511;
        float4 w = *(const float4*)(W_attn + (size_t)h * W3H + Hh + k);
        __half2 p0 = __floats2half2_rn(w.x, w.y);
        __half2 p1 = __floats2half2_rn(w.z, w.w);
        uint2 uu;
        uu.x = *reinterpret_cast<unsigned*>(&p0);
        uu.y = *reinterpret_cast<unsigned*>(&p1);
        *(uint2*)(g_w2h + i) = uu;
        return;
    }
    // ---- precompute: 8 threads per h-row, contiguous 128B per warp row-group ----
    __shared__ float sh[Hh];
    __shared__ float red[64][9];
    const int bx = blockIdx.x >> 3;              // 0..32
    const int hy = blockIdx.x & 7;               // 0..7
    sh[tx] = (bx < Bb) ? hidden[bx * Hh + tx] : W_cov[tx];
    __syncthreads();
    const int hl = tx >> 3, ks = tx & 7;
    const int h = hy * 64 + hl;
    const float* wr = W_attn + (size_t)h * W3H + (bx < Bb ? 0 : 2 * Hh);
    float a0 = 0.f, a1 = 0.f, a2 = 0.f, a3 = 0.f;
    #pragma unroll
    for (int j = 0; j < 16; j++) {
        const int k0 = j * 32 + ks * 4;
        float4 w = *(const float4*)(wr + k0);
        float4 s = *(const float4*)(sh + k0);
        a0 += w.x * s.x; a1 += w.y * s.y; a2 += w.z * s.z; a3 += w.w * s.w;
    }
    red[hl][ks] = (a0 + a1) + (a2 + a3);
    __syncthreads();
    if (tx < 64) {
        float s = 0.f;
        #pragma unroll
        for (int q = 0; q < 8; q++) s += red[tx][q];
        int hh = hy * 64 + tx;
        if (bx < Bb) g_u[bx * Hh + hh] = s + b_attn[hh];
        else         g_w3c[hh] = s;
    }
}

// ---------------- kernel 2: warp-MMA GEMM + fused epilogue -> scores ----------------
// 64-row T-tiles, 256 threads = 8 warps (2m x 4n), warp tile 32t x 32h.
// f32-accumulator MMA; double-buffered B; occupancy 2 CTAs/SM.
#define OFF_SU    0
#define OFF_SW3   2048
#define OFF_SV    4096
#define OFF_SRED  6144                 // 256 floats = 1024 B
#define OFF_A     8192                 // 8 k-sections x [64 rows x 128 B] = 65536
#define OFF_B     (8192 + 65536)       // 2 bufs x [128 rows x 128 B] = 32768
#define GEMM_SMEM (OFF_B + 32768)      // 106496

__global__ __launch_bounds__(256, 2)
void gemm_scores_kernel(const float* __restrict__ enc,
                        const float* __restrict__ coverage,
                        const float* __restrict__ v)
{
    extern __shared__ char smem[];
    const unsigned sb = smem_u32(smem);
    const int tx = threadIdx.x;
    const int wid = tx >> 5, l = tx & 31;
    const int mw = wid & 1, nw = wid >> 1;      // 2 m-warps x 4 n-warps
    const int b = blockIdx.y;
    const int t0 = blockIdx.x * 64;

    float* su  = (float*)(smem + OFF_SU);
    float* sw3 = (float*)(smem + OFF_SW3);
    float* sv  = (float*)(smem + OFF_SV);

    // ---- B chunk loader: chunk i -> (ht=i>>3, kc=i&7), buf i&1 (128h x 64k = 16KB) ----
    auto load_b = [&](int i) {
        const int ht = i >> 3, kc = i & 7;
        const unsigned bufo = sb + OFF_B + (unsigned)(i & 1) * 16384;
        #pragma unroll
        for (int j = 0; j < 4; j++) {
            const int idx = tx + j * 256;              // 0..1023
            const int row = idx >> 3;                  // 0..127
            const int seg = idx & 7;
            const __half* src = g_w2h + (size_t)(ht * 128 + row) * Hh + kc * 64 + seg * 8;
            CP_ASYNC16(bufo + swz((unsigned)(row * 128 + seg * 16)), src);
        }
    };

    load_b(0); CP_COMMIT();

    // ---- epilogue vectors ----
    for (int i = tx; i < Hh; i += 256) {
        su[i] = g_u[b * Hh + i]; sw3[i] = g_w3c[i]; sv[i] = v[i];
    }

    // ---- A tile: enc rows t0..t0+63 of batch b, fp32 -> fp16 swizzled smem ----
    {
        const int rs = tx >> 4, kg = tx & 15;
        #pragma unroll
        for (int rr = 0; rr < 4; rr++) {
            const int r = rr * 16 + rs;
            const float* rowp = enc + ((size_t)(t0 + r) * Bb + b) * Hh;
            #pragma unroll
            for (int kk = 0; kk < 8; kk++) {
                const int k0 = kk * 64 + kg * 4;
                float4 e = *(const float4*)(rowp + k0);
                __half2 p0 = __floats2half2_rn(e.x, e.y);
                __half2 p1 = __floats2half2_rn(e.z, e.w);
                uint2 uu;
                uu.x = *reinterpret_cast<unsigned*>(&p0);
                uu.y = *reinterpret_cast<unsigned*>(&p1);
                *(uint2*)(smem + OFF_A + kk * 8192 +
                          swz((unsigned)(r * 128 + (k0 & 63) * 2))) = uu;
            }
        }
    }

    // ---- per-lane ldmatrix address precompute ----
    unsigned aBase[2], aXor[2];
    {
        const int rA = mw * 32 + ((l >> 3) & 1) * 8 + (l & 7);
        #pragma unroll
        for (int mi = 0; mi < 2; mi++) {
            const int row = rA + mi * 16;
            aBase[mi] = sb + OFF_A + (unsigned)(row * 128);
            aXor[mi]  = (unsigned)((row & 7) << 4);
        }
    }
    const int cbA = ((l >> 4) & 1) * 8;
    unsigned bBase[2], bXor[2];
    {
        const int rB = nw * 32 + ((l >> 4) & 1) * 8 + (l & 7);
        #pragma unroll
        for (int nj = 0; nj < 2; nj++) {
            const int row = rB + nj * 16;
            bBase[nj] = sb + OFF_B + (unsigned)(row * 128);
            bXor[nj]  = (unsigned)((row & 7) << 4);
        }
    }
    const int cbB = ((l >> 3) & 1) * 8;

    float cov[4];
    #pragma unroll
    for (int mi = 0; mi < 2; mi++)
        #pragma unroll
        for (int half = 0; half < 2; half++)
            cov[mi * 2 + half] =
                coverage[b * Tt + t0 + mw * 32 + mi * 16 + (l >> 2) + half * 8];

    float acc[2][4][4];
    float sc[4] = {0.f, 0.f, 0.f, 0.f};
    const int c0 = (l & 3) * 2;

    // ---- main pipeline: 32 chunks (4 h-tiles x 8 k-chunks of 64), double buffer ----
    for (int i = 0; i < 32; i++) {
        CP_WAIT0();
        __syncthreads();
        if (i + 1 < 32) load_b(i + 1);
        CP_COMMIT();

        const int kc = i & 7, ht = i >> 3;
        if (kc == 0) {
            #pragma unroll
            for (int mi = 0; mi < 2; mi++)
                #pragma unroll
                for (int ni = 0; ni < 4; ni++)
                    #pragma unroll
                    for (int q = 0; q < 4; q++) acc[mi][ni][q] = 0.f;
        }

        const unsigned aS = (unsigned)kc * 8192;
        const unsigned bS = (unsigned)(i & 1) * 16384;
        #pragma unroll
        for (int s = 0; s < 4; s++) {
            const unsigned colA = (unsigned)((s * 16 + cbA) * 2);
            const unsigned colB = (unsigned)((s * 16 + cbB) * 2);
            unsigned av[2][4], bv[2][4];
            LDSM_X4(av[0], aBase[0] + aS + (colA ^ aXor[0]));
            LDSM_X4(av[1], aBase[1] + aS + (colA ^ aXor[1]));
            LDSM_X4(bv[0], bBase[0] + bS + (colB ^ bXor[0]));
            LDSM_X4(bv[1], bBase[1] + bS + (colB ^ bXor[1]));
            #pragma unroll
            for (int mi = 0; mi < 2; mi++) {
                MMA_F16(acc[mi][0], av[mi], bv[0][0], bv[0][1]);
                MMA_F16(acc[mi][1], av[mi], bv[0][2], bv[0][3]);
                MMA_F16(acc[mi][2], av[mi], bv[1][0], bv[1][1]);
                MMA_F16(acc[mi][3], av[mi], bv[1][2], bv[1][3]);
            }
        }

        if (kc == 7) {
            // epilogue for h-tile ht: energy + u + cov*w3c -> relu -> dot v
            #pragma unroll
            for (int ni = 0; ni < 4; ni++) {
                const int h = ht * 128 + nw * 32 + ni * 8 + c0;
                const float2 u2 = *(const float2*)&su[h];
                const float2 w2 = *(const float2*)&sw3[h];
                const float2 v2 = *(const float2*)&sv[h];
                #pragma unroll
                for (int mi = 0; mi < 2; mi++) {
                    float e0 = acc[mi][ni][0] + u2.x + cov[mi * 2] * w2.x;
                    float e1 = acc[mi][ni][1] + u2.y + cov[mi * 2] * w2.y;
                    sc[mi * 2] += v2.x * fmaxf(e0, 0.f) + v2.y * fmaxf(e1, 0.f);
                    float e2 = acc[mi][ni][2] + u2.x + cov[mi * 2 + 1] * w2.x;
                    float e3 = acc[mi][ni][3] + u2.y + cov[mi * 2 + 1] * w2.y;
                    sc[mi * 2 + 1] += v2.x * fmaxf(e2, 0.f) + v2.y * fmaxf(e3, 0.f);
                }
            }
        }
    }

    // ---- reduce: 4 lanes per row, then 4 n-warp groups ----
    #pragma unroll
    for (int q = 1; q < 4; q <<= 1)
        #pragma unroll
        for (int j = 0; j < 4; j++)
            sc[j] += __shfl_xor_sync(0xFFFFFFFFu, sc[j], q);

    float* sred = (float*)(smem + OFF_SRED);
    __syncthreads();
    if ((l & 3) == 0) {
        #pragma unroll
        for (int mi = 0; mi < 2; mi++)
            #pragma unroll
            for (int half = 0; half < 2; half++)
                sred[nw * 64 + mw * 32 + mi * 16 + (l >> 2) + half * 8] = sc[mi * 2 + half];
    }
    __syncthreads();
    if (tx < 64)
        g_scores[b * Tt + t0 + tx] =
            (sred[tx] + sred[64 + tx]) + (sred[128 + tx] + sred[192 + tx]);
}

// ---------------- kernel 3: softmax over T + coverage update ----------------
__global__ __launch_bounds__(512) void softmax_kernel(
    const float* __restrict__ coverage, float* __restrict__ out, int write_cov)
{
    __shared__ float red[16];
    const int b = blockIdx.x, tx = threadIdx.x;
    const int wi = tx >> 5, li = tx & 31;
    const float* s = g_scores + b * Tt;

    float4 x = ((const float4*)s)[tx];

    float m = fmaxf(fmaxf(x.x, x.y), fmaxf(x.z, x.w));
    #pragma unroll
    for (int q = 16; q > 0; q >>= 1) m = fmaxf(m, __shfl_xor_sync(0xFFFFFFFFu, m, q));
    if (li == 0) red[wi] = m;
    __syncthreads();
    if (tx < 32) {
        float mm = (tx < 16) ? red[tx] : -3.0e38f;
        #pragma unroll
        for (int q = 8; q > 0; q >>= 1) mm = fmaxf(mm, __shfl_xor_sync(0xFFFFFFFFu, mm, q));
        if (tx == 0) red[0] = mm;
    }
    __syncthreads();
    m = red[0];

    float4 e;
    e.x = __expf(x.x - m); e.y = __expf(x.y - m);
    e.z = __expf(x.z - m); e.w = __expf(x.w - m);
    float sum = (e.x + e.y) + (e.z + e.w);
    #pragma unroll
    for (int q = 16; q > 0; q >>= 1) sum += __shfl_xor_sync(0xFFFFFFFFu, sum, q);
    __syncthreads();
    if (li == 0) red[wi] = sum;
    __syncthreads();
    if (tx < 32) {
        float ss = (tx < 16) ? red[tx] : 0.f;
        #pragma unroll
        for (int q = 8; q > 0; q >>= 1) ss += __shfl_xor_sync(0xFFFFFFFFu, ss, q);
        if (tx == 0) red[0] = ss;
    }
    __syncthreads();
    const float inv = 1.f / red[0];

    float4 w;
    w.x = e.x * inv; w.y = e.y * inv; w.z = e.z * inv; w.w = e.w * inv;
    ((float4*)(out + b * Tt))[tx] = w;
    if (write_cov) {
        float4 c = ((const float4*)(coverage + b * Tt))[tx];
        c.x += w.x; c.y += w.y; c.z += w.z; c.w += w.w;
        ((float4*)(out + Bb * Tt + b * Tt))[tx] = c;
    }
}

// ---------------- launch ----------------
extern "C" void kernel_launch(void* const* d_in, const int* in_sizes, int n_in,
                              void* d_out, int out_size) {
    const float* hidden   = (const float*)d_in[0];
    const float* enc      = (const float*)d_in[1];
    const float* coverage = (const float*)d_in[2];
    const float* W_attn   = (const float*)d_in[3];
    const float* b_attn   = (const float*)d_in[4];
    const float* v        = (const float*)d_in[5];
    const float* W_cov    = (const float*)d_in[6];
    float* out = (float*)d_out;

    cudaFuncSetAttribute(gemm_scores_kernel,
                         cudaFuncAttributeMaxDynamicSharedMemorySize, GEMM_SMEM);

    prep_kernel<<<392, 512>>>(hidden, W_attn, b_attn, W_cov);
    gemm_scores_kernel<<<dim3(Tt / 64, Bb), 256, GEMM_SMEM>>>(enc, coverage, v);

    const int write_cov = (out_size >= 2 * Bb * Tt) ? 1 : 0;
    softmax_kernel<<<Bb, 512>>>(coverage, out, write_cov);
}